// round 12
// baseline (speedup 1.0000x reference)
#include <cuda_runtime.h>
#include <cuda_bf16.h>
#include <cstdint>

// Steerable encoder, fused single kernel, register-direct MMA fragments:
//   out_c[r][j] = sum_i (ey[r][i]*w_c[i]) * ex[j][i]
// Grid (3 channels x 96 K-splits) = 288 CTAs, co-resident at occ 2.
// Each lane computes its own m16n8k16 fragment elements (exp -> bf16 hi/lo
// pack) directly in registers: NO smem staging, NO ldmatrix, NO mainloop
// __syncthreads. Grid barrier + fused reduce/normalize at the end.

#define NA     128
#define NPIX   (NA * NA)
#define NPTS   8192
#define NSPLIT 96
#define KSTEPS 512                 // 8192 / 16
#define NCTAS  (3 * NSPLIT)        // 288 (<= 148*2 residency)
#define MAXI   96                  // max i's per CTA (6 steps * 16)

__device__ float g_part[3 * NSPLIT * NPIX];       // 18.9 MB
__device__ unsigned int g_arrive  = 0;
__device__ unsigned int g_release = 0;

// ---------------- helpers ----------------
__device__ __forceinline__ void mma_bf16(float* d, const uint32_t* a, const uint32_t* b) {
    asm volatile("mma.sync.aligned.m16n8k16.row.col.f32.bf16.bf16.f32 "
                 "{%0,%1,%2,%3}, {%4,%5,%6,%7}, {%8,%9}, {%0,%1,%2,%3};"
                 : "+f"(d[0]), "+f"(d[1]), "+f"(d[2]), "+f"(d[3])
                 : "r"(a[0]), "r"(a[1]), "r"(a[2]), "r"(a[3]), "r"(b[0]), "r"(b[1]));
}
// Split pair (a -> low half, b -> high half) into packed bf16x2 hi (truncated)
// and lo (residual, round-to-nearest).
__device__ __forceinline__ void pack_pair(float a, float b, uint32_t& hi, uint32_t& lo) {
    uint32_t ua = __float_as_uint(a), ub = __float_as_uint(b);
    hi = __byte_perm(ua, ub, 0x7632);
    float la = a - __uint_as_float(ua & 0xFFFF0000u);
    float lb = b - __uint_as_float(ub & 0xFFFF0000u);
    asm("cvt.rn.bf16x2.f32 %0, %1, %2;" : "=r"(lo) : "f"(lb), "f"(la));
}

// ---------------- fused kernel ----------------
__global__ __launch_bounds__(256, 2)
void fused_kernel(const float* __restrict__ X, const float* __restrict__ Y,
                  float* __restrict__ out)
{
    __shared__ float spx[MAXI], spy[MAXI], sy0[MAXI], sy1[MAXI];
    __shared__ unsigned int sh_rel0;

    const int tid  = threadIdx.x;
    const int lane = tid & 31, wid = tid >> 5;
    const int c = blockIdx.x, s = blockIdx.y;
    const int lo = (KSTEPS * s) / NSPLIT, hi = (KSTEPS * (s + 1)) / NSPLIT;
    const int cnt = (hi - lo) * 16;

    if (tid == 0) sh_rel0 = *(volatile unsigned int*)&g_release;

    // stage this CTA's point parameters
    for (int idx = tid; idx < cnt; idx += 256) {
        int i = lo * 16 + idx;
        float2 xp = ((const float2*)X)[i];
        float2 yp = ((const float2*)Y)[i];
        spx[idx] = xp.x; spy[idx] = xp.y;
        sy0[idx] = yp.x; sy1[idx] = yp.y;
    }

    const float step = 4.0f / 127.0f;
    const int wm = wid & 3, wn = wid >> 2;      // warp tile: rows [wm*32,+32), cols [wn*64,+64)
    const int gr = lane >> 2, tig = lane & 3;   // fragment lane coords

    // hoisted row/col coordinates
    float yA[2][2];
    #pragma unroll
    for (int mt = 0; mt < 2; mt++)
        #pragma unroll
        for (int h = 0; h < 2; h++)
            yA[mt][h] = 2.0f - (float)(wm * 32 + mt * 16 + gr + 8 * h) * step;
    const float xbase = -2.0f + (float)(wn * 64 + gr) * step;   // + nt*8*step per n-tile
    const float xstep8 = 8.0f * step;

    float acc[2][8][4];
    #pragma unroll
    for (int a = 0; a < 2; a++)
        #pragma unroll
        for (int b = 0; b < 8; b++)
            #pragma unroll
            for (int d = 0; d < 4; d++) acc[a][b][d] = 0.0f;

    __syncthreads();

    const int iofs = 2 * tig;    // lane's k-columns: iofs, iofs+1, iofs+8, iofs+9

    for (int ks = lo; ks < hi; ks++) {
        const int lb = (ks - lo) * 16;

        // lane's 4 point-parameter sets
        float pxv[4], pyv[4], wv[4];
        #pragma unroll
        for (int t = 0; t < 4; t++) {
            int il = lb + iofs + (t & 1) + (t >> 1) * 8;
            pxv[t] = spx[il];
            pyv[t] = spy[il];
            wv[t]  = (c == 0) ? 1.0f : ((c == 1) ? sy0[il] : sy1[il]);
        }

        // ---- A fragments: ey(row,i) * w_c, hi/lo packed ----
        uint32_t ah[2][4], al[2][4];
        #pragma unroll
        for (int mt = 0; mt < 2; mt++) {
            float e[2][4];
            #pragma unroll
            for (int h = 0; h < 2; h++)
                #pragma unroll
                for (int t = 0; t < 4; t++) {
                    float d = yA[mt][h] - pyv[t];
                    e[h][t] = __expf(-0.5f * d * d) * wv[t];
                }
            pack_pair(e[0][0], e[0][1], ah[mt][0], al[mt][0]);
            pack_pair(e[1][0], e[1][1], ah[mt][1], al[mt][1]);
            pack_pair(e[0][2], e[0][3], ah[mt][2], al[mt][2]);
            pack_pair(e[1][2], e[1][3], ah[mt][3], al[mt][3]);
        }

        // ---- B fragments + MMAs, per n-tile ----
        #pragma unroll
        for (int nt = 0; nt < 8; nt++) {
            const float xj = xbase + (float)nt * xstep8;
            float eb[4];
            #pragma unroll
            for (int t = 0; t < 4; t++) {
                float d = xj - pxv[t];
                eb[t] = __expf(-0.5f * d * d);
            }
            uint32_t bh[2], bl[2];
            pack_pair(eb[0], eb[1], bh[0], bl[0]);
            pack_pair(eb[2], eb[3], bh[1], bl[1]);
            #pragma unroll
            for (int mt = 0; mt < 2; mt++) {
                float* D = acc[mt][nt];
                mma_bf16(D, ah[mt], bh);   // Ah*Bh
                mma_bf16(D, ah[mt], bl);   // Ah*Bl
                mma_bf16(D, al[mt], bh);   // Al*Bh
            }
        }
    }

    // ---- write partial plane [c][s][r][j] ----
    float* plane = g_part + (c * NSPLIT + s) * NPIX;
    #pragma unroll
    for (int mt = 0; mt < 2; mt++) {
        #pragma unroll
        for (int nt = 0; nt < 8; nt++) {
            int m0 = wm * 32 + mt * 16 + gr;
            int j0 = wn * 64 + nt * 8 + 2 * tig;
            *(float2*)(plane + m0 * NA + j0)       = make_float2(acc[mt][nt][0], acc[mt][nt][1]);
            *(float2*)(plane + (m0 + 8) * NA + j0) = make_float2(acc[mt][nt][2], acc[mt][nt][3]);
        }
    }

    // ---- grid barrier (all 288 CTAs co-resident at occ 2) ----
    __threadfence();
    __syncthreads();
    if (tid == 0) {
        unsigned int old = atomicAdd(&g_arrive, 1u);
        if (old == NCTAS - 1) {
            g_arrive = 0;
            __threadfence();
            atomicAdd(&g_release, 1u);
        }
        while (*(volatile unsigned int*)&g_release == sh_rel0) { }
    }
    __syncthreads();
    __threadfence();

    // ---- fused reduce + normalize (partials L2-hot) ----
    const int bid = blockIdx.y * gridDim.x + blockIdx.x;    // 0..287
    const int p = bid * 256 + tid;
    if (p < NPIX) {
        float s0 = 0.0f, s1 = 0.0f, s2 = 0.0f;
        #pragma unroll 12
        for (int sl = 0; sl < NSPLIT; sl++) {
            s0 += __ldcg(&g_part[(0 * NSPLIT + sl) * NPIX + p]);
            s1 += __ldcg(&g_part[(1 * NSPLIT + sl) * NPIX + p]);
            s2 += __ldcg(&g_part[(2 * NSPLIT + sl) * NPIX + p]);
        }
        float r = 1.0f / s0;
        out[p]            = s0;
        out[NPIX + p]     = s1 * r;
        out[2 * NPIX + p] = s2 * r;
    }
}

extern "C" void kernel_launch(void* const* d_in, const int* in_sizes, int n_in,
                              void* d_out, int out_size)
{
    const float* X = (const float*)d_in[0];
    const float* Y = (const float*)d_in[1];
    float* out = (float*)d_out;

    fused_kernel<<<dim3(3, NSPLIT), 256>>>(X, Y, out);
}

// round 13
// speedup vs baseline: 1.1379x; 1.1379x over previous
#include <cuda_runtime.h>
#include <cuda_bf16.h>
#include <cstdint>

// Steerable encoder, fused single kernel, register-direct TF32 MMA:
//   out_c[r][j] = sum_i (ey[r][i]*w_c[i]) * ex[j][i]
// Grid (3 channels x 96 K-splits) = 288 CTAs, co-resident at occ 2.
// Each lane computes its own m16n8k8 TF32 fragment elements (exp -> cvt.rna)
// directly in registers: no smem staging, no ldmatrix, no packing, single
// MMA product (TF32 statistical precision ~1e-4 << 1e-3 tolerance).
// Grid barrier + fused reduce/normalize at the end.

#define NA     128
#define NPIX   (NA * NA)
#define NPTS   8192
#define NSPLIT 96
#define KSTEPS 1024                // 8192 / 8 (k8 steps)
#define NCTAS  (3 * NSPLIT)        // 288 (<= 148*2 residency)
#define MAXI   96                  // max i's per CTA (11 steps * 8 = 88)

__device__ float g_part[3 * NSPLIT * NPIX];       // 18.9 MB
__device__ unsigned int g_arrive  = 0;
__device__ unsigned int g_release = 0;

// ---------------- helpers ----------------
__device__ __forceinline__ void mma_tf32(float* d, const uint32_t* a, const uint32_t* b) {
    asm volatile("mma.sync.aligned.m16n8k8.row.col.f32.tf32.tf32.f32 "
                 "{%0,%1,%2,%3}, {%4,%5,%6,%7}, {%8,%9}, {%0,%1,%2,%3};"
                 : "+f"(d[0]), "+f"(d[1]), "+f"(d[2]), "+f"(d[3])
                 : "r"(a[0]), "r"(a[1]), "r"(a[2]), "r"(a[3]), "r"(b[0]), "r"(b[1]));
}
__device__ __forceinline__ uint32_t cvt_tf32(float v) {
    uint32_t r;
    asm("cvt.rna.tf32.f32 %0, %1;" : "=r"(r) : "f"(v));
    return r;
}
// exp(-0.5 d^2) = 2^(d^2 * -0.5*log2(e))
__device__ __forceinline__ float expn(float d) {
    return exp2f(d * d * (-0.72134752044448170f));
}

// ---------------- fused kernel ----------------
__global__ __launch_bounds__(256, 2)
void fused_kernel(const float* __restrict__ X, const float* __restrict__ Y,
                  float* __restrict__ out)
{
    __shared__ float spx[MAXI], spy[MAXI], sy0[MAXI], sy1[MAXI];
    __shared__ unsigned int sh_rel0;

    const int tid  = threadIdx.x;
    const int lane = tid & 31, wid = tid >> 5;
    const int c = blockIdx.x, s = blockIdx.y;
    const int lo = (KSTEPS * s) / NSPLIT, hi = (KSTEPS * (s + 1)) / NSPLIT;
    const int cnt = (hi - lo) * 8;

    if (tid == 0) sh_rel0 = *(volatile unsigned int*)&g_release;

    // stage this CTA's point parameters
    for (int idx = tid; idx < cnt; idx += 256) {
        int i = lo * 8 + idx;
        float2 xp = ((const float2*)X)[i];
        float2 yp = ((const float2*)Y)[i];
        spx[idx] = xp.x; spy[idx] = xp.y;
        sy0[idx] = yp.x; sy1[idx] = yp.y;
    }

    const float step = 4.0f / 127.0f;
    const int wm = wid & 3, wn = wid >> 2;      // warp tile: rows [wm*32,+32), cols [wn*64,+64)
    const int gr = lane >> 2, tig = lane & 3;   // fragment lane coords

    // hoisted row/col coordinates
    float yA[2][2];
    #pragma unroll
    for (int mt = 0; mt < 2; mt++)
        #pragma unroll
        for (int h = 0; h < 2; h++)
            yA[mt][h] = 2.0f - (float)(wm * 32 + mt * 16 + gr + 8 * h) * step;
    const float xbase  = -2.0f + (float)(wn * 64 + gr) * step;
    const float xstep8 = 8.0f * step;

    float acc[2][8][4];
    #pragma unroll
    for (int a = 0; a < 2; a++)
        #pragma unroll
        for (int b = 0; b < 8; b++)
            #pragma unroll
            for (int d = 0; d < 4; d++) acc[a][b][d] = 0.0f;

    __syncthreads();

    for (int ks = lo; ks < hi; ks++) {
        const int lb = (ks - lo) * 8;
        const int i0 = lb + tig, i1 = i0 + 4;   // lane's two k-slots: tig, tig+4

        const float px0 = spx[i0], px1 = spx[i1];
        const float py0 = spy[i0], py1 = spy[i1];
        float w0, w1;
        if (c == 0)      { w0 = 1.0f;    w1 = 1.0f;    }
        else if (c == 1) { w0 = sy0[i0]; w1 = sy0[i1]; }
        else             { w0 = sy1[i0]; w1 = sy1[i1]; }

        // ---- A fragments: ey(row, p) * w ----
        uint32_t afr[2][4];
        #pragma unroll
        for (int mt = 0; mt < 2; mt++) {
            afr[mt][0] = cvt_tf32(expn(yA[mt][0] - py0) * w0);  // (gr,   k=tig)
            afr[mt][1] = cvt_tf32(expn(yA[mt][1] - py0) * w0);  // (gr+8, k=tig)
            afr[mt][2] = cvt_tf32(expn(yA[mt][0] - py1) * w1);  // (gr,   k=tig+4)
            afr[mt][3] = cvt_tf32(expn(yA[mt][1] - py1) * w1);  // (gr+8, k=tig+4)
        }

        // ---- B fragments + MMAs per n-tile ----
        #pragma unroll
        for (int nt = 0; nt < 8; nt++) {
            const float xj = xbase + (float)nt * xstep8;        // col = wn*64+nt*8+gr
            uint32_t bfr[2];
            bfr[0] = cvt_tf32(expn(xj - px0));                  // (k=tig,   col)
            bfr[1] = cvt_tf32(expn(xj - px1));                  // (k=tig+4, col)
            mma_tf32(acc[0][nt], afr[0], bfr);
            mma_tf32(acc[1][nt], afr[1], bfr);
        }
    }

    // ---- write partial plane [c][s][r][j] ----
    float* plane = g_part + (c * NSPLIT + s) * NPIX;
    #pragma unroll
    for (int mt = 0; mt < 2; mt++) {
        #pragma unroll
        for (int nt = 0; nt < 8; nt++) {
            int m0 = wm * 32 + mt * 16 + gr;
            int j0 = wn * 64 + nt * 8 + 2 * tig;
            *(float2*)(plane + m0 * NA + j0)       = make_float2(acc[mt][nt][0], acc[mt][nt][1]);
            *(float2*)(plane + (m0 + 8) * NA + j0) = make_float2(acc[mt][nt][2], acc[mt][nt][3]);
        }
    }

    // ---- grid barrier (all 288 CTAs co-resident at occ 2) ----
    __threadfence();
    __syncthreads();
    if (tid == 0) {
        unsigned int old = atomicAdd(&g_arrive, 1u);
        if (old == NCTAS - 1) {
            g_arrive = 0;
            __threadfence();
            atomicAdd(&g_release, 1u);
        }
        while (*(volatile unsigned int*)&g_release == sh_rel0) { }
    }
    __syncthreads();
    __threadfence();

    // ---- fused reduce + normalize (partials L2-hot) ----
    const int bid = blockIdx.y * gridDim.x + blockIdx.x;    // 0..287
    const int p = bid * 256 + tid;
    if (p < NPIX) {
        float s0 = 0.0f, s1 = 0.0f, s2 = 0.0f;
        #pragma unroll 12
        for (int sl = 0; sl < NSPLIT; sl++) {
            s0 += __ldcg(&g_part[(0 * NSPLIT + sl) * NPIX + p]);
            s1 += __ldcg(&g_part[(1 * NSPLIT + sl) * NPIX + p]);
            s2 += __ldcg(&g_part[(2 * NSPLIT + sl) * NPIX + p]);
        }
        float r = 1.0f / s0;
        out[p]            = s0;
        out[NPIX + p]     = s1 * r;
        out[2 * NPIX + p] = s2 * r;
    }
}

extern "C" void kernel_launch(void* const* d_in, const int* in_sizes, int n_in,
                              void* d_out, int out_size)
{
    const float* X = (const float*)d_in[0];
    const float* Y = (const float*)d_in[1];
    float* out = (float*)d_out;

    fused_kernel<<<dim3(3, NSPLIT), 256>>>(X, Y, out);
}

// round 14
// speedup vs baseline: 1.2774x; 1.1226x over previous
#include <cuda_runtime.h>
#include <cuda_bf16.h>
#include <cstdint>

// Steerable encoder, fused single kernel, register-direct TF32 MMA,
// j-split CTAs (32 accumulators) + geometric exp recurrence.
//   out_c[r][j] = sum_i (ey[r][i]*w_c[i]) * ex[j][i]
// Grid (3 ch x 2 j-halves x 49 K-splits) = 294 CTAs, co-resident at occ 2.

#define NA     128
#define NPIX   (NA * NA)
#define NPTS   8192
#define NSPLIT 49
#define KSTEPS 1024                // 8192 / 8 (k8 steps)
#define NCTAS  (6 * NSPLIT)        // 294 (<= 296 occ-2 residency)
#define MAXI   176                 // max i's per CTA (22 steps * 8)

__device__ float g_part[3 * NSPLIT * NPIX];       // 9.6 MB
__device__ unsigned int g_arrive  = 0;
__device__ unsigned int g_release = 0;

#define STEP   (4.0f / 127.0f)
#define KEXP   0.72134752044448170f        // 0.5*log2(e)
#define DELTA  (8.0f * STEP)               // fragment row/col spacing

// ---------------- helpers ----------------
__device__ __forceinline__ void mma_tf32(float* d, const uint32_t* a, const uint32_t* b) {
    asm volatile("mma.sync.aligned.m16n8k8.row.col.f32.tf32.tf32.f32 "
                 "{%0,%1,%2,%3}, {%4,%5,%6,%7}, {%8,%9}, {%0,%1,%2,%3};"
                 : "+f"(d[0]), "+f"(d[1]), "+f"(d[2]), "+f"(d[3])
                 : "r"(a[0]), "r"(a[1]), "r"(a[2]), "r"(a[3]), "r"(b[0]), "r"(b[1]));
}
__device__ __forceinline__ uint32_t cvt_tf32(float v) {
    uint32_t r;
    asm("cvt.rna.tf32.f32 %0, %1;" : "=r"(r) : "f"(v));
    return r;
}

// 4 Gaussian values at coords x0 + t*sgn*DELTA (t=0..3) vs point p:
//   e[t] = exp2(-KEXP*(x0 + t*sgn*DELTA - p)^2), via geometric recurrence.
__device__ __forceinline__ void exp_chain4(float d0, float c1, float q, float* e) {
    // e0 = 2^(-k d0^2); r0 = 2^(c1*d0 - k*DELTA^2)
    float e0 = exp2f(d0 * d0 * (-KEXP));
    float r0 = exp2f(fmaf(c1, d0, -KEXP * DELTA * DELTA));
    e[0] = e0;
    e[1] = e[0] * r0;  float r1 = r0 * q;
    e[2] = e[1] * r1;  float r2 = r1 * q;
    e[3] = e[2] * r2;
}

// ---------------- fused kernel ----------------
__global__ __launch_bounds__(256, 2)
void fused_kernel(const float* __restrict__ X, const float* __restrict__ Y,
                  float* __restrict__ out)
{
    __shared__ float spx[MAXI], spy[MAXI], sy0[MAXI], sy1[MAXI];
    __shared__ unsigned int sh_rel0;

    const int tid  = threadIdx.x;
    const int lane = tid & 31, wid = tid >> 5;
    const int c  = blockIdx.x % 3;              // channel
    const int jh = blockIdx.x / 3;              // j half (0/1)
    const int s  = blockIdx.y;                  // K split
    const int lo = (KSTEPS * s) / NSPLIT, hi = (KSTEPS * (s + 1)) / NSPLIT;
    const int cnt = (hi - lo) * 8;

    if (tid == 0) sh_rel0 = *(volatile unsigned int*)&g_release;

    // stage this CTA's point parameters
    for (int idx = tid; idx < cnt; idx += 256) {
        int i = lo * 8 + idx;
        float2 xp = ((const float2*)X)[i];
        float2 yp = ((const float2*)Y)[i];
        spx[idx] = xp.x; spy[idx] = xp.y;
        sy0[idx] = yp.x; sy1[idx] = yp.y;
    }

    const int wm = wid & 3, wn = wid >> 2;      // warp tile: rows [wm*32,+32), cols [wn*32,+32)
    const int gr = lane >> 2, tig = lane & 3;   // fragment lane coords

    // first row/col coordinate for this lane's chains
    const float y0 = 2.0f - (float)(wm * 32 + gr) * STEP;            // rows y0 - t*DELTA
    const float x0 = -2.0f + (float)(jh * 64 + wn * 32 + gr) * STEP; // cols x0 + t*DELTA
    const float q  = exp2f(-2.0f * KEXP * DELTA * DELTA);
    const float c1A =  2.0f * KEXP * DELTA;     // rows: spacing -DELTA
    const float c1B = -2.0f * KEXP * DELTA;     // cols: spacing +DELTA

    float acc[2][4][4];
    #pragma unroll
    for (int a = 0; a < 2; a++)
        #pragma unroll
        for (int b = 0; b < 4; b++)
            #pragma unroll
            for (int d = 0; d < 4; d++) acc[a][b][d] = 0.0f;

    __syncthreads();

    for (int ks = lo; ks < hi; ks++) {
        const int lb = (ks - lo) * 8;
        const int i0 = lb + tig, i1 = i0 + 4;   // lane's two k-slots

        const float px0 = spx[i0], px1 = spx[i1];
        const float py0 = spy[i0], py1 = spy[i1];
        float w0, w1;
        if (c == 0)      { w0 = 1.0f;    w1 = 1.0f;    }
        else if (c == 1) { w0 = sy0[i0]; w1 = sy0[i1]; }
        else             { w0 = sy1[i0]; w1 = sy1[i1]; }

        // ---- A chains: 4 row-values per point (rows gr+{0,8,16,24}) ----
        float ea0[4], ea1[4];
        exp_chain4(y0 - py0, c1A, q, ea0);
        exp_chain4(y0 - py1, c1A, q, ea1);
        uint32_t afr[2][4];
        #pragma unroll
        for (int mt = 0; mt < 2; mt++) {
            afr[mt][0] = cvt_tf32(ea0[2 * mt + 0] * w0);   // (row, k=tig)
            afr[mt][1] = cvt_tf32(ea0[2 * mt + 1] * w0);   // (row+8, k=tig)
            afr[mt][2] = cvt_tf32(ea1[2 * mt + 0] * w1);   // (row, k=tig+4)
            afr[mt][3] = cvt_tf32(ea1[2 * mt + 1] * w1);   // (row+8, k=tig+4)
        }

        // ---- B chains: 4 col-values per point (cols gr + nt*8) ----
        float eb0[4], eb1[4];
        exp_chain4(x0 - px0, c1B, q, eb0);
        exp_chain4(x0 - px1, c1B, q, eb1);

        #pragma unroll
        for (int nt = 0; nt < 4; nt++) {
            uint32_t bfr[2];
            bfr[0] = cvt_tf32(eb0[nt]);                    // (k=tig,   col)
            bfr[1] = cvt_tf32(eb1[nt]);                    // (k=tig+4, col)
            mma_tf32(acc[0][nt], afr[0], bfr);
            mma_tf32(acc[1][nt], afr[1], bfr);
        }
    }

    // ---- write partial plane [c][s][r][j] ----
    float* plane = g_part + (c * NSPLIT + s) * NPIX;
    #pragma unroll
    for (int mt = 0; mt < 2; mt++) {
        #pragma unroll
        for (int nt = 0; nt < 4; nt++) {
            int m0 = wm * 32 + mt * 16 + gr;
            int j0 = jh * 64 + wn * 32 + nt * 8 + 2 * tig;
            *(float2*)(plane + m0 * NA + j0)       = make_float2(acc[mt][nt][0], acc[mt][nt][1]);
            *(float2*)(plane + (m0 + 8) * NA + j0) = make_float2(acc[mt][nt][2], acc[mt][nt][3]);
        }
    }

    // ---- grid barrier (all 294 CTAs co-resident at occ 2) ----
    __threadfence();
    __syncthreads();
    if (tid == 0) {
        unsigned int old = atomicAdd(&g_arrive, 1u);
        if (old == NCTAS - 1) {
            g_arrive = 0;
            __threadfence();
            atomicAdd(&g_release, 1u);
        }
        while (*(volatile unsigned int*)&g_release == sh_rel0) { }
    }
    __syncthreads();
    __threadfence();

    // ---- fused reduce + normalize (partials L2-hot) ----
    const int bid = blockIdx.y * gridDim.x + blockIdx.x;    // 0..293
    const int p = bid * 256 + tid;
    if (p < NPIX) {
        float s0 = 0.0f, s1 = 0.0f, s2 = 0.0f;
        #pragma unroll 7
        for (int sl = 0; sl < NSPLIT; sl++) {
            s0 += __ldcg(&g_part[(0 * NSPLIT + sl) * NPIX + p]);
            s1 += __ldcg(&g_part[(1 * NSPLIT + sl) * NPIX + p]);
            s2 += __ldcg(&g_part[(2 * NSPLIT + sl) * NPIX + p]);
        }
        float r = 1.0f / s0;
        out[p]            = s0;
        out[NPIX + p]     = s1 * r;
        out[2 * NPIX + p] = s2 * r;
    }
}

extern "C" void kernel_launch(void* const* d_in, const int* in_sizes, int n_in,
                              void* d_out, int out_size)
{
    const float* X = (const float*)d_in[0];
    const float* Y = (const float*)d_in[1];
    float* out = (float*)d_out;

    fused_kernel<<<dim3(6, NSPLIT), 256>>>(X, Y, out);
}